// round 10
// baseline (speedup 1.0000x reference)
#include <cuda_runtime.h>
#include <cuda_bf16.h>
#include <math.h>
#include <stdint.h>

#define TOK   65536
#define CH    256
#define HEADS 8
#define HD    32
#define WS    8
#define MLPH  1024

// ---------------- scratch (static device globals; no allocation) -----------
__device__ float          g_qkv [TOK * 3 * CH];
__device__ float          g_x   [TOK * CH];
__device__ float          g_y   [TOK * CH];
__device__ __nv_bfloat16  g_lnh [TOK * CH];
__device__ __nv_bfloat16  g_lnl [TOK * CH];
__device__ __nv_bfloat16  g_ath [TOK * CH];
__device__ __nv_bfloat16  g_atl [TOK * CH];
__device__ __nv_bfloat16  g_mph [TOK * MLPH];
__device__ __nv_bfloat16  g_mpl [TOK * MLPH];
#define WT_BLK 786432
__device__ __nv_bfloat16  g_wth [2 * WT_BLK];
__device__ __nv_bfloat16  g_wtl [2 * WT_BLK];

// ======================= small PTX helpers =================================
__device__ __forceinline__ uint32_t smem_u32(const void* p) {
    uint32_t a;
    asm("{ .reg .u64 t; cvta.to.shared.u64 t, %1; cvt.u32.u64 %0, t; }" : "=r"(a) : "l"(p));
    return a;
}
__device__ __forceinline__ void cp16(uint32_t s, const void* g) {
    asm volatile("cp.async.ca.shared.global [%0], [%1], 16;" :: "r"(s), "l"(g));
}
#define CP_COMMIT() asm volatile("cp.async.commit_group;" ::: "memory")
#define CP_WAIT(n)  asm volatile("cp.async.wait_group %0;" :: "n"(n) : "memory")

__device__ __forceinline__ void ld_x4(uint32_t* r, uint32_t addr) {
    asm volatile("ldmatrix.sync.aligned.m8n8.x4.shared.b16 {%0,%1,%2,%3}, [%4];"
                 : "=r"(r[0]), "=r"(r[1]), "=r"(r[2]), "=r"(r[3]) : "r"(addr));
}
__device__ __forceinline__ void mma16816(float* c, const uint32_t* a, const uint32_t* b) {
    asm volatile("mma.sync.aligned.m16n8k16.row.col.f32.bf16.bf16.f32 "
                 "{%0,%1,%2,%3}, {%4,%5,%6,%7}, {%8,%9}, {%0,%1,%2,%3};"
                 : "+f"(c[0]), "+f"(c[1]), "+f"(c[2]), "+f"(c[3])
                 : "r"(a[0]), "r"(a[1]), "r"(a[2]), "r"(a[3]), "r"(b[0]), "r"(b[1]));
}
__device__ __forceinline__ void split_bf16(float v, __nv_bfloat16& h, __nv_bfloat16& l) {
    h = __float2bfloat16(v);
    l = __float2bfloat16(v - __bfloat162float(h));
}
__device__ __forceinline__ float gelu_exact(float x) {
    return 0.5f * x * (1.0f + erff(x * 0.7071067811865476f));
}

// ============ LayerNorm: 4 tokens/block, 64 threads/token, float4 ==========
__global__ __launch_bounds__(256)
void ln_kernel(const float* __restrict__ in, const float* __restrict__ gam,
               const float* __restrict__ bet,
               __nv_bfloat16* __restrict__ oh, __nv_bfloat16* __restrict__ ol) {
    const int tid = threadIdx.x;
    const int g = tid >> 6;
    const int l64 = tid & 63;
    const int w = (tid >> 5) & 1;
    const int tok = blockIdx.x * 4 + g;

    __shared__ float redm[4][2];
    __shared__ float redv[4][2];

    const size_t base = (size_t)tok * CH + l64 * 4;
    float4 v = *(const float4*)(in + base);

    float s = v.x + v.y + v.z + v.w;
    #pragma unroll
    for (int o = 16; o; o >>= 1) s += __shfl_xor_sync(0xffffffffu, s, o);
    if ((tid & 31) == 0) redm[g][w] = s;
    __syncthreads();
    const float mu = (redm[g][0] + redm[g][1]) * (1.0f / CH);

    float dx = v.x - mu, dy = v.y - mu, dz = v.z - mu, dw = v.w - mu;
    s = dx * dx + dy * dy + dz * dz + dw * dw;
    #pragma unroll
    for (int o = 16; o; o >>= 1) s += __shfl_xor_sync(0xffffffffu, s, o);
    if ((tid & 31) == 0) redv[g][w] = s;
    __syncthreads();
    const float inv = rsqrtf((redv[g][0] + redv[g][1]) * (1.0f / CH) + 1e-5f);

    const float4 gm = *(const float4*)(gam + l64 * 4);
    const float4 bt = *(const float4*)(bet + l64 * 4);
    float o0 = dx * inv * gm.x + bt.x;
    float o1 = dy * inv * gm.y + bt.y;
    float o2 = dz * inv * gm.z + bt.z;
    float o3 = dw * inv * gm.w + bt.w;

    __nv_bfloat16 h[4], lo[4];
    split_bf16(o0, h[0], lo[0]); split_bf16(o1, h[1], lo[1]);
    split_bf16(o2, h[2], lo[2]); split_bf16(o3, h[3], lo[3]);
    *(uint2*)(oh + base) = *(uint2*)h;
    *(uint2*)(ol + base) = *(uint2*)lo;
}

// ========== weight prep: W[K,N] -> Wt_hi[N,K], Wt_lo[N,K] (bf16) ===========
__global__ void transpose_split(const float* __restrict__ W, __nv_bfloat16* __restrict__ th,
                                __nv_bfloat16* __restrict__ tl, int K, int N) {
    __shared__ float t[32][33];
    int nb = blockIdx.x << 5, kb = blockIdx.y << 5;
    #pragma unroll
    for (int i = 0; i < 32; i += 8)
        t[threadIdx.y + i][threadIdx.x] = W[(size_t)(kb + threadIdx.y + i) * N + nb + threadIdx.x];
    __syncthreads();
    #pragma unroll
    for (int i = 0; i < 32; i += 8) {
        float v = t[threadIdx.x][threadIdx.y + i];
        __nv_bfloat16 h, l;
        split_bf16(v, h, l);
        size_t off = (size_t)(nb + threadIdx.y + i) * K + kb + threadIdx.x;
        th[off] = h; tl[off] = l;
    }
}

// ======================= split-bf16 HMMA GEMM ==============================
// CTA 128x128, warps 2m x 4n (64x32 tiles), 4-stage cp.async, one sync/chunk.
// C = A @ Wt^T (3-pass: Ah*Bh + Ah*Bl + Al*Bh), bias + epilogue.
// EPI: 0 = fp32 out;  1 = GELU -> (hi,lo) bf16 out;  2 = +res -> fp32 out.
#define TS 40                         // smem row stride in halves (80 B)
#define TILE_B (128 * TS * 2)         // 10240 B per tile
#define STAGE_B (4 * TILE_B)          // Ah, Al, Bh, Bl
#define NSTAGE 4
#define SM_BIAS (NSTAGE * STAGE_B)
#define SM_DYN  (SM_BIAS + 512)

template <int EPI>
__global__ __launch_bounds__(256, 1)
void tc_gemm(const __nv_bfloat16* __restrict__ Ah, const __nv_bfloat16* __restrict__ Al,
             const __nv_bfloat16* __restrict__ Bh, const __nv_bfloat16* __restrict__ Bl,
             const float* __restrict__ bias, const float* __restrict__ res,
             float* __restrict__ out, __nv_bfloat16* __restrict__ outh,
             __nv_bfloat16* __restrict__ outl, int M, int N, int K) {
    extern __shared__ char sm[];
    const uint32_t sb = smem_u32(sm);
    const int tid = threadIdx.x, wid = tid >> 5, lane = tid & 31;
    const int n0 = blockIdx.x << 7, m0 = blockIdx.y << 7;
    const int mw = wid >> 2, nw = wid & 3;          // warp grid 2x4 -> 64x32 tiles

    float* sbias = (float*)(sm + SM_BIAS);
    if (tid < 128) sbias[tid] = bias[n0 + tid];

    const int lrow = tid >> 2, lc = tid & 3;
    auto load_stage = [&](int s, int kc) {
        const int k0 = kc << 5;
        uint32_t base = sb + s * STAGE_B;
        #pragma unroll
        for (int i = 0; i < 2; i++) {
            int row = lrow + i * 64;
            uint32_t so = row * (TS * 2) + lc * 16;
            size_t ga = (size_t)(m0 + row) * K + k0 + lc * 8;
            size_t gb = (size_t)(n0 + row) * K + k0 + lc * 8;
            cp16(base + 0 * TILE_B + so, Ah + ga);
            cp16(base + 1 * TILE_B + so, Al + ga);
            cp16(base + 2 * TILE_B + so, Bh + gb);
            cp16(base + 3 * TILE_B + so, Bl + gb);
        }
    };

    float acc[4][4][4] = {};

    const int li = lane & 7, lm = lane >> 3;
    const uint32_t aRB = (mw * 64 + (lm & 1) * 8 + li) * (TS * 2) + ((lm >> 1) * 8) * 2;
    const uint32_t bRB = (nw * 32 + (lm >> 1) * 8 + li) * (TS * 2) + ((lm & 1) * 8) * 2;

    const int nch = K >> 5;
    load_stage(0, 0); CP_COMMIT();
    load_stage(1, 1); CP_COMMIT();
    if (nch > 2) { load_stage(2, 2); CP_COMMIT(); }

    int s = 0;
    for (int kc = 0; kc < nch; kc++) {
        if (kc + 2 < nch)      CP_WAIT(2);
        else if (kc + 1 < nch) CP_WAIT(1);
        else                   CP_WAIT(0);
        __syncthreads();

        const uint32_t sA  = sb + s * STAGE_B;
        const uint32_t sAl = sA + TILE_B;
        const uint32_t sB  = sA + 2 * TILE_B;
        const uint32_t sBl = sA + 3 * TILE_B;

        #pragma unroll
        for (int kk = 0; kk < 2; kk++) {
            const uint32_t ko = kk * 32;
            uint32_t ah[16], al[16], bh[8], bl[8];
            #pragma unroll
            for (int mg = 0; mg < 4; mg++) ld_x4(ah + mg * 4, sA + aRB + mg * 16 * (TS * 2) + ko);
            #pragma unroll
            for (int ng = 0; ng < 2; ng++) ld_x4(bh + ng * 4, sB + bRB + ng * 16 * (TS * 2) + ko);
            #pragma unroll
            for (int mg = 0; mg < 4; mg++)
                #pragma unroll
                for (int j = 0; j < 4; j++)
                    mma16816(acc[mg][j], ah + mg * 4, bh + (j >> 1) * 4 + (j & 1) * 2);
            #pragma unroll
            for (int ng = 0; ng < 2; ng++) ld_x4(bl + ng * 4, sBl + bRB + ng * 16 * (TS * 2) + ko);
            #pragma unroll
            for (int mg = 0; mg < 4; mg++)
                #pragma unroll
                for (int j = 0; j < 4; j++)
                    mma16816(acc[mg][j], ah + mg * 4, bl + (j >> 1) * 4 + (j & 1) * 2);
            #pragma unroll
            for (int mg = 0; mg < 4; mg++) ld_x4(al + mg * 4, sAl + aRB + mg * 16 * (TS * 2) + ko);
            #pragma unroll
            for (int mg = 0; mg < 4; mg++)
                #pragma unroll
                for (int j = 0; j < 4; j++)
                    mma16816(acc[mg][j], al + mg * 4, bh + (j >> 1) * 4 + (j & 1) * 2);
        }

        if (kc + 3 < nch) { load_stage((kc + 3) % NSTAGE, kc + 3); CP_COMMIT(); }
        s = (s + 1 == NSTAGE) ? 0 : s + 1;
    }
    __syncthreads();

    // ---- epilogue: regs -> smem (fp32) -> coalesced gmem ----
    float* sacc = (float*)sm;                       // 128 x 132 floats
    const int fr = lane >> 2, fc = (lane & 3) * 2;
    #pragma unroll
    for (int mg = 0; mg < 4; mg++)
        #pragma unroll
        for (int j = 0; j < 4; j++) {
            int row = mw * 64 + mg * 16 + fr;
            int col = nw * 32 + j * 8 + fc;
            sacc[row * 132 + col]           = acc[mg][j][0];
            sacc[row * 132 + col + 1]       = acc[mg][j][1];
            sacc[(row + 8) * 132 + col]     = acc[mg][j][2];
            sacc[(row + 8) * 132 + col + 1] = acc[mg][j][3];
        }
    __syncthreads();

    const float4 b4 = *(const float4*)&sbias[lane * 4];
    #pragma unroll 4
    for (int it = 0; it < 16; it++) {
        int r = it * 8 + wid;
        float4 v = *(const float4*)&sacc[r * 132 + lane * 4];
        v.x += b4.x; v.y += b4.y; v.z += b4.z; v.w += b4.w;
        size_t off = (size_t)(m0 + r) * N + n0 + lane * 4;
        if (EPI == 0) {
            *(float4*)&out[off] = v;
        } else if (EPI == 1) {
            v.x = gelu_exact(v.x); v.y = gelu_exact(v.y);
            v.z = gelu_exact(v.z); v.w = gelu_exact(v.w);
            __nv_bfloat16 h[4], l[4];
            split_bf16(v.x, h[0], l[0]); split_bf16(v.y, h[1], l[1]);
            split_bf16(v.z, h[2], l[2]); split_bf16(v.w, h[3], l[3]);
            *(uint2*)&outh[off] = *(uint2*)h;
            *(uint2*)&outl[off] = *(uint2*)l;
        } else {
            float4 rv = *(const float4*)&res[off];
            v.x += rv.x; v.y += rv.y; v.z += rv.z; v.w += rv.w;
            *(float4*)&out[off] = v;
        }
    }
}

// ======================= windowed attention (fp32, emits hi/lo) ============
template <int SHIFT>
__global__ __launch_bounds__(64)
void attn_kernel(const float* __restrict__ qkv, const float* __restrict__ rpb,
                 __nv_bfloat16* __restrict__ outh, __nv_bfloat16* __restrict__ outl) {
    const int head = blockIdx.x, win = blockIdx.y, b = blockIdx.z;
    const int wy = win >> 3, wx = win & 7;
    const int n = threadIdx.x;
    const int r = n >> 3, c = n & 7;

    __shared__ float Ks[64][HD];
    __shared__ float Vs[64][HD];
    __shared__ float sbias[225];
    __shared__ int   scode[64];

    const int sy = wy * WS + r, sx = wx * WS + c;
    const int y = (sy + SHIFT) & 63;
    const int x = (sx + SHIFT) & 63;
    const int t = b * 4096 + y * 64 + x;

    const float4* base = (const float4*)(qkv + (size_t)t * (3 * CH) + head * HD);
    float4 qv[8];
    #pragma unroll
    for (int i = 0; i < 8; i++) {
        float4 u = base[i];
        qv[i].x = u.x * 0.17677669529663687f;
        qv[i].y = u.y * 0.17677669529663687f;
        qv[i].z = u.z * 0.17677669529663687f;
        qv[i].w = u.w * 0.17677669529663687f;
    }
    #pragma unroll
    for (int i = 0; i < 8; i++) *(float4*)&Ks[n][i * 4] = base[64 + i];
    #pragma unroll
    for (int i = 0; i < 8; i++) *(float4*)&Vs[n][i * 4] = base[128 + i];

    if (SHIFT) {
        int ry = sy < 56 ? 0 : (sy < 60 ? 1 : 2);
        int rx = sx < 56 ? 0 : (sx < 60 ? 1 : 2);
        scode[n] = ry * 3 + rx;
    }
    for (int i = n; i < 225; i += 64) sbias[i] = rpb[i * HEADS + head];
    __syncthreads();

    float s[64];
    const int mycode = SHIFT ? scode[n] : 0;
    #pragma unroll
    for (int m = 0; m < 64; m++) {
        const float4* kp = (const float4*)&Ks[m][0];
        float a0 = 0.f, a1 = 0.f, a2 = 0.f, a3 = 0.f;
        #pragma unroll
        for (int i = 0; i < 8; i++) {
            float4 k4 = kp[i];
            a0 += qv[i].x * k4.x;
            a1 += qv[i].y * k4.y;
            a2 += qv[i].z * k4.z;
            a3 += qv[i].w * k4.w;
        }
        int r2 = m >> 3, c2 = m & 7;
        float a = (a0 + a1) + (a2 + a3) + sbias[(r - r2 + 7) * 15 + (c - c2 + 7)];
        if (SHIFT) { if (mycode != scode[m]) a -= 100.0f; }
        s[m] = a;
    }
    float mx = -1e30f;
    #pragma unroll
    for (int m = 0; m < 64; m++) mx = fmaxf(mx, s[m]);
    float sum = 0.f;
    #pragma unroll
    for (int m = 0; m < 64; m++) { s[m] = __expf(s[m] - mx); sum += s[m]; }
    const float inv = 1.0f / sum;

    float4 av[8] = {};
    #pragma unroll
    for (int m = 0; m < 64; m++) {
        const float p = s[m];
        const float4* vp = (const float4*)&Vs[m][0];
        #pragma unroll
        for (int i = 0; i < 8; i++) {
            float4 v4 = vp[i];
            av[i].x += p * v4.x;
            av[i].y += p * v4.y;
            av[i].z += p * v4.z;
            av[i].w += p * v4.w;
        }
    }
    size_t ob = (size_t)t * CH + head * HD;
    #pragma unroll
    for (int i = 0; i < 8; i++) {
        __nv_bfloat16 h[4], l[4];
        split_bf16(av[i].x * inv, h[0], l[0]);
        split_bf16(av[i].y * inv, h[1], l[1]);
        split_bf16(av[i].z * inv, h[2], l[2]);
        split_bf16(av[i].w * inv, h[3], l[3]);
        *(uint2*)(outh + ob + i * 4) = *(uint2*)h;
        *(uint2*)(outl + ob + i * 4) = *(uint2*)l;
    }
}

// ======================= host orchestration =================================
struct Bufs {
    float *qkv, *xb, *yb;
    __nv_bfloat16 *lnh, *lnl, *ath, *atl, *mph, *mpl, *wth, *wtl;
};

static inline void launch_gemm(int epi, const __nv_bfloat16* Ah, const __nv_bfloat16* Al,
                               const __nv_bfloat16* Bh, const __nv_bfloat16* Bl,
                               const float* bias, const float* res, float* out,
                               __nv_bfloat16* oh, __nv_bfloat16* ol, int N, int K) {
    dim3 grid(N / 128, TOK / 128);
    if (epi == 0)      tc_gemm<0><<<grid, 256, SM_DYN>>>(Ah, Al, Bh, Bl, bias, res, out, oh, ol, TOK, N, K);
    else if (epi == 1) tc_gemm<1><<<grid, 256, SM_DYN>>>(Ah, Al, Bh, Bl, bias, res, out, oh, ol, TOK, N, K);
    else               tc_gemm<2><<<grid, 256, SM_DYN>>>(Ah, Al, Bh, Bl, bias, res, out, oh, ol, TOK, N, K);
}

extern "C" void kernel_launch(void* const* d_in, const int* in_sizes, int n_in,
                              void* d_out, int out_size) {
    const float* x = (const float*)d_in[0];
    const float* p0[13];
    const float* p1[13];
    for (int i = 0; i < 13; i++) p0[i] = (const float*)d_in[1 + i];
    for (int i = 0; i < 13; i++) p1[i] = (const float*)d_in[14 + i];

    Bufs b;
    cudaGetSymbolAddress((void**)&b.qkv, g_qkv);
    cudaGetSymbolAddress((void**)&b.xb,  g_x);
    cudaGetSymbolAddress((void**)&b.yb,  g_y);
    cudaGetSymbolAddress((void**)&b.lnh, g_lnh);
    cudaGetSymbolAddress((void**)&b.lnl, g_lnl);
    cudaGetSymbolAddress((void**)&b.ath, g_ath);
    cudaGetSymbolAddress((void**)&b.atl, g_atl);
    cudaGetSymbolAddress((void**)&b.mph, g_mph);
    cudaGetSymbolAddress((void**)&b.mpl, g_mpl);
    cudaGetSymbolAddress((void**)&b.wth, g_wth);
    cudaGetSymbolAddress((void**)&b.wtl, g_wtl);

    cudaFuncSetAttribute(tc_gemm<0>, cudaFuncAttributeMaxDynamicSharedMemorySize, SM_DYN);
    cudaFuncSetAttribute(tc_gemm<1>, cudaFuncAttributeMaxDynamicSharedMemorySize, SM_DYN);
    cudaFuncSetAttribute(tc_gemm<2>, cudaFuncAttributeMaxDynamicSharedMemorySize, SM_DYN);

    // ---- weight prep: transpose + hi/lo split ----
    const float* srcs[2][4] = {{p0[2], p0[5], p0[9], p0[11]}, {p1[2], p1[5], p1[9], p1[11]}};
    const int KK[4]  = {256, 256, 256, 1024};
    const int NN[4]  = {768, 256, 1024, 256};
    const int OFF[4] = {0, 196608, 262144, 524288};
    for (int blk = 0; blk < 2; blk++)
        for (int w = 0; w < 4; w++)
            transpose_split<<<dim3(NN[w] / 32, KK[w] / 32), dim3(32, 8)>>>(
                srcs[blk][w], b.wth + blk * WT_BLK + OFF[w], b.wtl + blk * WT_BLK + OFF[w],
                KK[w], NN[w]);

    for (int blk = 0; blk < 2; blk++) {
        const float* const* p = blk ? p1 : p0;
        const float* xin = blk ? b.xb : x;
        float* xout = blk ? b.yb : b.xb;
        __nv_bfloat16* wh = b.wth + blk * WT_BLK;
        __nv_bfloat16* wl = b.wtl + blk * WT_BLK;
        float* fin = blk ? (float*)d_out : b.xb;

        ln_kernel<<<TOK / 4, 256>>>(xin, p[0], p[1], b.lnh, b.lnl);
        launch_gemm(0, b.lnh, b.lnl, wh + 0, wl + 0, p[3], nullptr, b.qkv, nullptr, nullptr, 768, 256);
        if (blk)
            attn_kernel<4><<<dim3(HEADS, 64, 16), 64>>>(b.qkv, p[4], b.ath, b.atl);
        else
            attn_kernel<0><<<dim3(HEADS, 64, 16), 64>>>(b.qkv, p[4], b.ath, b.atl);
        launch_gemm(2, b.ath, b.atl, wh + 196608, wl + 196608, p[6], xin, xout, nullptr, nullptr, 256, 256);
        ln_kernel<<<TOK / 4, 256>>>(xout, p[7], p[8], b.lnh, b.lnl);
        launch_gemm(1, b.lnh, b.lnl, wh + 262144, wl + 262144, p[10], nullptr, nullptr, b.mph, b.mpl, 1024, 256);
        launch_gemm(2, b.mph, b.mpl, wh + 524288, wl + 524288, p[12], xout, fin, nullptr, nullptr, 256, 1024);
    }
}

// round 15
// speedup vs baseline: 1.7938x; 1.7938x over previous
#include <cuda_runtime.h>
#include <cuda_fp16.h>
#include <math.h>
#include <stdint.h>

#define TOK   65536
#define CH    256
#define HEADS 8
#define HD    32
#define WS    8
#define MLPH  1024

// ---------------- scratch (static device globals; no allocation) -----------
__device__ float   g_qkv [TOK * 3 * CH];
__device__ float   g_x   [TOK * CH];
__device__ float   g_y   [TOK * CH];
__device__ __half  g_ln  [TOK * CH];
__device__ __half  g_at  [TOK * CH];
__device__ __half  g_mp  [TOK * MLPH];
#define WT_BLK 786432
__device__ __half  g_wt  [2 * WT_BLK];

// ======================= small PTX helpers =================================
__device__ __forceinline__ uint32_t smem_u32(const void* p) {
    uint32_t a;
    asm("{ .reg .u64 t; cvta.to.shared.u64 t, %1; cvt.u32.u64 %0, t; }" : "=r"(a) : "l"(p));
    return a;
}
__device__ __forceinline__ void cp16(uint32_t s, const void* g) {
    asm volatile("cp.async.ca.shared.global [%0], [%1], 16;" :: "r"(s), "l"(g));
}
#define CP_COMMIT() asm volatile("cp.async.commit_group;" ::: "memory")
#define CP_WAIT(n)  asm volatile("cp.async.wait_group %0;" :: "n"(n) : "memory")

__device__ __forceinline__ void ld_x4(uint32_t* r, uint32_t addr) {
    asm volatile("ldmatrix.sync.aligned.m8n8.x4.shared.b16 {%0,%1,%2,%3}, [%4];"
                 : "=r"(r[0]), "=r"(r[1]), "=r"(r[2]), "=r"(r[3]) : "r"(addr));
}
__device__ __forceinline__ void mma16816(float* c, const uint32_t* a, const uint32_t* b) {
    asm volatile("mma.sync.aligned.m16n8k16.row.col.f32.f16.f16.f32 "
                 "{%0,%1,%2,%3}, {%4,%5,%6,%7}, {%8,%9}, {%0,%1,%2,%3};"
                 : "+f"(c[0]), "+f"(c[1]), "+f"(c[2]), "+f"(c[3])
                 : "r"(a[0]), "r"(a[1]), "r"(a[2]), "r"(a[3]), "r"(b[0]), "r"(b[1]));
}
__device__ __forceinline__ float gelu_exact(float x) {
    return 0.5f * x * (1.0f + erff(x * 0.7071067811865476f));
}

// ============ LayerNorm: 4 tokens/block, 64 threads/token, float4 ==========
__global__ __launch_bounds__(256)
void ln_kernel(const float* __restrict__ in, const float* __restrict__ gam,
               const float* __restrict__ bet, __half* __restrict__ oh) {
    const int tid = threadIdx.x;
    const int g = tid >> 6;
    const int l64 = tid & 63;
    const int w = (tid >> 5) & 1;
    const int tok = blockIdx.x * 4 + g;

    __shared__ float redm[4][2];
    __shared__ float redv[4][2];

    const size_t base = (size_t)tok * CH + l64 * 4;
    float4 v = *(const float4*)(in + base);

    float s = v.x + v.y + v.z + v.w;
    #pragma unroll
    for (int o = 16; o; o >>= 1) s += __shfl_xor_sync(0xffffffffu, s, o);
    if ((tid & 31) == 0) redm[g][w] = s;
    __syncthreads();
    const float mu = (redm[g][0] + redm[g][1]) * (1.0f / CH);

    float dx = v.x - mu, dy = v.y - mu, dz = v.z - mu, dw = v.w - mu;
    s = dx * dx + dy * dy + dz * dz + dw * dw;
    #pragma unroll
    for (int o = 16; o; o >>= 1) s += __shfl_xor_sync(0xffffffffu, s, o);
    if ((tid & 31) == 0) redv[g][w] = s;
    __syncthreads();
    const float inv = rsqrtf((redv[g][0] + redv[g][1]) * (1.0f / CH) + 1e-5f);

    const float4 gm = *(const float4*)(gam + l64 * 4);
    const float4 bt = *(const float4*)(bet + l64 * 4);
    __half h[4];
    h[0] = __float2half_rn(dx * inv * gm.x + bt.x);
    h[1] = __float2half_rn(dy * inv * gm.y + bt.y);
    h[2] = __float2half_rn(dz * inv * gm.z + bt.z);
    h[3] = __float2half_rn(dw * inv * gm.w + bt.w);
    *(uint2*)(oh + base) = *(uint2*)h;
}

// ========== weight prep: W[K,N] -> Wt[N,K] (fp16) ==========================
__global__ void transpose_half(const float* __restrict__ W, __half* __restrict__ th,
                               int K, int N) {
    __shared__ float t[32][33];
    int nb = blockIdx.x << 5, kb = blockIdx.y << 5;
    #pragma unroll
    for (int i = 0; i < 32; i += 8)
        t[threadIdx.y + i][threadIdx.x] = W[(size_t)(kb + threadIdx.y + i) * N + nb + threadIdx.x];
    __syncthreads();
    #pragma unroll
    for (int i = 0; i < 32; i += 8) {
        size_t off = (size_t)(nb + threadIdx.y + i) * K + kb + threadIdx.x;
        th[off] = __float2half_rn(t[threadIdx.x][threadIdx.y + i]);
    }
}

// ======================= fp16 HMMA GEMM ====================================
// CTA 128x128, warps 2m x 4n (64x32 tiles), 4-stage cp.async, 2 CTAs/SM.
// C = A @ Wt^T + bias (+epi).  EPI: 0 fp32; 1 GELU->fp16; 2 +res fp32.
#define TS 40                         // smem row stride in halves (80 B)
#define TILE_B (128 * TS * 2)         // 10240 B per tile
#define STAGE_B (2 * TILE_B)          // A, B
#define NSTAGE 4
#define SM_BIAS (NSTAGE * STAGE_B)
#define SM_DYN  (SM_BIAS + 512)

template <int EPI>
__global__ __launch_bounds__(256, 2)
void tc_gemm(const __half* __restrict__ Ah, const __half* __restrict__ Bh,
             const float* __restrict__ bias, const float* __restrict__ res,
             float* __restrict__ out, __half* __restrict__ outh,
             int M, int N, int K) {
    extern __shared__ char sm[];
    const uint32_t sb = smem_u32(sm);
    const int tid = threadIdx.x, wid = tid >> 5, lane = tid & 31;
    const int n0 = blockIdx.x << 7, m0 = blockIdx.y << 7;
    const int mw = wid >> 2, nw = wid & 3;          // warp grid 2x4 -> 64x32 tiles

    float* sbias = (float*)(sm + SM_BIAS);
    if (tid < 128) sbias[tid] = bias[n0 + tid];

    const int lrow = tid >> 2, lc = tid & 3;
    auto load_stage = [&](int s, int kc) {
        const int k0 = kc << 5;
        uint32_t base = sb + s * STAGE_B;
        #pragma unroll
        for (int i = 0; i < 2; i++) {
            int row = lrow + i * 64;
            uint32_t so = row * (TS * 2) + lc * 16;
            cp16(base + so, Ah + (size_t)(m0 + row) * K + k0 + lc * 8);
            cp16(base + TILE_B + so, Bh + (size_t)(n0 + row) * K + k0 + lc * 8);
        }
    };

    float acc[4][4][4] = {};

    const int li = lane & 7, lm = lane >> 3;
    const uint32_t aRB = (mw * 64 + (lm & 1) * 8 + li) * (TS * 2) + ((lm >> 1) * 8) * 2;
    const uint32_t bRB = (nw * 32 + (lm >> 1) * 8 + li) * (TS * 2) + ((lm & 1) * 8) * 2;

    const int nch = K >> 5;
    load_stage(0, 0); CP_COMMIT();
    load_stage(1, 1); CP_COMMIT();
    if (nch > 2) { load_stage(2, 2); CP_COMMIT(); }

    int s = 0;
    for (int kc = 0; kc < nch; kc++) {
        if (kc + 2 < nch)      CP_WAIT(2);
        else if (kc + 1 < nch) CP_WAIT(1);
        else                   CP_WAIT(0);
        __syncthreads();

        const uint32_t sA = sb + s * STAGE_B;
        const uint32_t sB = sA + TILE_B;

        #pragma unroll
        for (int kk = 0; kk < 2; kk++) {
            const uint32_t ko = kk * 32;
            uint32_t ah[16], bh[8];
            #pragma unroll
            for (int mg = 0; mg < 4; mg++) ld_x4(ah + mg * 4, sA + aRB + mg * 16 * (TS * 2) + ko);
            #pragma unroll
            for (int ng = 0; ng < 2; ng++) ld_x4(bh + ng * 4, sB + bRB + ng * 16 * (TS * 2) + ko);
            #pragma unroll
            for (int mg = 0; mg < 4; mg++)
                #pragma unroll
                for (int j = 0; j < 4; j++)
                    mma16816(acc[mg][j], ah + mg * 4, bh + (j >> 1) * 4 + (j & 1) * 2);
        }

        if (kc + 3 < nch) { load_stage((kc + 3) % NSTAGE, kc + 3); CP_COMMIT(); }
        s = (s + 1 == NSTAGE) ? 0 : s + 1;
    }
    __syncthreads();

    // ---- epilogue: regs -> smem (fp32) -> coalesced gmem ----
    float* sacc = (float*)sm;                       // 128 x 132 floats
    const int fr = lane >> 2, fc = (lane & 3) * 2;
    #pragma unroll
    for (int mg = 0; mg < 4; mg++)
        #pragma unroll
        for (int j = 0; j < 4; j++) {
            int row = mw * 64 + mg * 16 + fr;
            int col = nw * 32 + j * 8 + fc;
            sacc[row * 132 + col]           = acc[mg][j][0];
            sacc[row * 132 + col + 1]       = acc[mg][j][1];
            sacc[(row + 8) * 132 + col]     = acc[mg][j][2];
            sacc[(row + 8) * 132 + col + 1] = acc[mg][j][3];
        }
    __syncthreads();

    const float4 b4 = *(const float4*)&sbias[lane * 4];
    #pragma unroll 4
    for (int it = 0; it < 16; it++) {
        int r = it * 8 + wid;
        float4 v = *(const float4*)&sacc[r * 132 + lane * 4];
        v.x += b4.x; v.y += b4.y; v.z += b4.z; v.w += b4.w;
        size_t off = (size_t)(m0 + r) * N + n0 + lane * 4;
        if (EPI == 0) {
            *(float4*)&out[off] = v;
        } else if (EPI == 1) {
            __half h[4];
            h[0] = __float2half_rn(gelu_exact(v.x));
            h[1] = __float2half_rn(gelu_exact(v.y));
            h[2] = __float2half_rn(gelu_exact(v.z));
            h[3] = __float2half_rn(gelu_exact(v.w));
            *(uint2*)&outh[off] = *(uint2*)h;
        } else {
            float4 rv = *(const float4*)&res[off];
            v.x += rv.x; v.y += rv.y; v.z += rv.z; v.w += rv.w;
            *(float4*)&out[off] = v;
        }
    }
}

// ======================= windowed attention (fp32, emits fp16) =============
template <int SHIFT>
__global__ __launch_bounds__(64)
void attn_kernel(const float* __restrict__ qkv, const float* __restrict__ rpb,
                 __half* __restrict__ outh) {
    const int head = blockIdx.x, win = blockIdx.y, b = blockIdx.z;
    const int wy = win >> 3, wx = win & 7;
    const int n = threadIdx.x;
    const int r = n >> 3, c = n & 7;

    __shared__ float Ks[64][HD];
    __shared__ float Vs[64][HD];
    __shared__ float sbias[225];
    __shared__ int   scode[64];

    const int sy = wy * WS + r, sx = wx * WS + c;
    const int y = (sy + SHIFT) & 63;
    const int x = (sx + SHIFT) & 63;
    const int t = b * 4096 + y * 64 + x;

    const float4* base = (const float4*)(qkv + (size_t)t * (3 * CH) + head * HD);
    float4 qv[8];
    #pragma unroll
    for (int i = 0; i < 8; i++) {
        float4 u = base[i];
        qv[i].x = u.x * 0.17677669529663687f;
        qv[i].y = u.y * 0.17677669529663687f;
        qv[i].z = u.z * 0.17677669529663687f;
        qv[i].w = u.w * 0.17677669529663687f;
    }
    #pragma unroll
    for (int i = 0; i < 8; i++) *(float4*)&Ks[n][i * 4] = base[64 + i];
    #pragma unroll
    for (int i = 0; i < 8; i++) *(float4*)&Vs[n][i * 4] = base[128 + i];

    if (SHIFT) {
        int ry = sy < 56 ? 0 : (sy < 60 ? 1 : 2);
        int rx = sx < 56 ? 0 : (sx < 60 ? 1 : 2);
        scode[n] = ry * 3 + rx;
    }
    for (int i = n; i < 225; i += 64) sbias[i] = rpb[i * HEADS + head];
    __syncthreads();

    float s[64];
    const int mycode = SHIFT ? scode[n] : 0;
    #pragma unroll
    for (int m = 0; m < 64; m++) {
        const float4* kp = (const float4*)&Ks[m][0];
        float a0 = 0.f, a1 = 0.f, a2 = 0.f, a3 = 0.f;
        #pragma unroll
        for (int i = 0; i < 8; i++) {
            float4 k4 = kp[i];
            a0 += qv[i].x * k4.x;
            a1 += qv[i].y * k4.y;
            a2 += qv[i].z * k4.z;
            a3 += qv[i].w * k4.w;
        }
        int r2 = m >> 3, c2 = m & 7;
        float a = (a0 + a1) + (a2 + a3) + sbias[(r - r2 + 7) * 15 + (c - c2 + 7)];
        if (SHIFT) { if (mycode != scode[m]) a -= 100.0f; }
        s[m] = a;
    }
    float mx = -1e30f;
    #pragma unroll
    for (int m = 0; m < 64; m++) mx = fmaxf(mx, s[m]);
    float sum = 0.f;
    #pragma unroll
    for (int m = 0; m < 64; m++) { s[m] = __expf(s[m] - mx); sum += s[m]; }
    const float inv = 1.0f / sum;

    float4 av[8] = {};
    #pragma unroll
    for (int m = 0; m < 64; m++) {
        const float p = s[m];
        const float4* vp = (const float4*)&Vs[m][0];
        #pragma unroll
        for (int i = 0; i < 8; i++) {
            float4 v4 = vp[i];
            av[i].x += p * v4.x;
            av[i].y += p * v4.y;
            av[i].z += p * v4.z;
            av[i].w += p * v4.w;
        }
    }
    size_t ob = (size_t)t * CH + head * HD;
    #pragma unroll
    for (int i = 0; i < 8; i++) {
        __half h[4];
        h[0] = __float2half_rn(av[i].x * inv);
        h[1] = __float2half_rn(av[i].y * inv);
        h[2] = __float2half_rn(av[i].z * inv);
        h[3] = __float2half_rn(av[i].w * inv);
        *(uint2*)(outh + ob + i * 4) = *(uint2*)h;
    }
}

// ======================= host orchestration =================================
static inline void launch_gemm(int epi, const __half* A, const __half* B,
                               const float* bias, const float* res, float* out,
                               __half* oh, int N, int K) {
    dim3 grid(N / 128, TOK / 128);
    if (epi == 0)      tc_gemm<0><<<grid, 256, SM_DYN>>>(A, B, bias, res, out, oh, TOK, N, K);
    else if (epi == 1) tc_gemm<1><<<grid, 256, SM_DYN>>>(A, B, bias, res, out, oh, TOK, N, K);
    else               tc_gemm<2><<<grid, 256, SM_DYN>>>(A, B, bias, res, out, oh, TOK, N, K);
}

extern "C" void kernel_launch(void* const* d_in, const int* in_sizes, int n_in,
                              void* d_out, int out_size) {
    const float* x = (const float*)d_in[0];
    const float* p0[13];
    const float* p1[13];
    for (int i = 0; i < 13; i++) p0[i] = (const float*)d_in[1 + i];
    for (int i = 0; i < 13; i++) p1[i] = (const float*)d_in[14 + i];

    float *qkv, *xb, *yb;
    __half *lnb, *atb, *mpb, *wt;
    cudaGetSymbolAddress((void**)&qkv, g_qkv);
    cudaGetSymbolAddress((void**)&xb,  g_x);
    cudaGetSymbolAddress((void**)&yb,  g_y);
    cudaGetSymbolAddress((void**)&lnb, g_ln);
    cudaGetSymbolAddress((void**)&atb, g_at);
    cudaGetSymbolAddress((void**)&mpb, g_mp);
    cudaGetSymbolAddress((void**)&wt,  g_wt);

    cudaFuncSetAttribute(tc_gemm<0>, cudaFuncAttributeMaxDynamicSharedMemorySize, SM_DYN);
    cudaFuncSetAttribute(tc_gemm<1>, cudaFuncAttributeMaxDynamicSharedMemorySize, SM_DYN);
    cudaFuncSetAttribute(tc_gemm<2>, cudaFuncAttributeMaxDynamicSharedMemorySize, SM_DYN);

    // ---- weight prep: transpose fp32 -> fp16 [N,K] ----
    const float* srcs[2][4] = {{p0[2], p0[5], p0[9], p0[11]}, {p1[2], p1[5], p1[9], p1[11]}};
    const int KK[4]  = {256, 256, 256, 1024};
    const int NN[4]  = {768, 256, 1024, 256};
    const int OFF[4] = {0, 196608, 262144, 524288};
    for (int blk = 0; blk < 2; blk++)
        for (int w = 0; w < 4; w++)
            transpose_half<<<dim3(NN[w] / 32, KK[w] / 32), dim3(32, 8)>>>(
                srcs[blk][w], wt + blk * WT_BLK + OFF[w], KK[w], NN[w]);

    for (int blk = 0; blk < 2; blk++) {
        const float* const* p = blk ? p1 : p0;
        const float* xin = blk ? xb : x;
        float* xout = blk ? yb : xb;
        __half* wh = wt + blk * WT_BLK;
        float* fin = blk ? (float*)d_out : xb;

        ln_kernel<<<TOK / 4, 256>>>(xin, p[0], p[1], lnb);
        launch_gemm(0, lnb, wh + 0, p[3], nullptr, qkv, nullptr, 768, 256);
        if (blk)
            attn_kernel<4><<<dim3(HEADS, 64, 16), 64>>>(qkv, p[4], atb);
        else
            attn_kernel<0><<<dim3(HEADS, 64, 16), 64>>>(qkv, p[4], atb);
        launch_gemm(2, atb, wh + 196608, p[6], xin, xout, nullptr, 256, 256);
        ln_kernel<<<TOK / 4, 256>>>(xout, p[7], p[8], lnb);
        launch_gemm(1, lnb, wh + 262144, p[10], nullptr, nullptr, mpb, 1024, 256);
        launch_gemm(2, mpb, wh + 524288, p[12], xout, fin, nullptr, 256, 1024);
    }
}